// round 12
// baseline (speedup 1.0000x reference)
#include <cuda_runtime.h>
#include <cuda_bf16.h>
#include <cstdint>

// Problem constants (SpaAggregator): B=16384, K=32, N=1e6, F=E=128
#define KNBR 32
#define FDIM 128
#define EDIM 128
#define NTBL 1000000

#define NTHR   256       // 8 warps: 4 producer + 4 consumer
#define TNODES 8         // nodes per stolen tile -> 2048 tiles
#define ATP    10        // As_t node-dim stride (floats); k-stride 40B (8B-aligned pairs)
#define GRID   592       // 148 SMs * 4 CTAs (persistent, work-stealing)

// smem (bytes): blkslot 128 | As_t 2*128*10*4 = 10240 | sidx 8*32*4 = 1024
#define SMEM_BLK  0
#define SMEM_AT   128
#define SMEM_IDX  (128 + 10240)
#define SMEM_TOT  (128 + 10240 + 1024)

__device__ unsigned int g_ctr;   // work-stealing tile counter

__global__ void spa_zero_ctr() { g_ctr = 0u; }

__device__ __forceinline__ unsigned long long ffma2(
    unsigned long long a, unsigned long long b, unsigned long long c)
{
    unsigned long long d;
    asm("fma.rn.f32x2 %0, %1, %2, %3;" : "=l"(d) : "l"(a), "l"(b), "l"(c));
    return d;
}
__device__ __forceinline__ unsigned long long add2(
    unsigned long long a, unsigned long long b)
{
    unsigned long long d;
    asm("add.rn.f32x2 %0, %1, %2;" : "=l"(d) : "l"(a), "l"(b));
    return d;
}
__device__ __forceinline__ unsigned long long pack2(float x, float y)
{
    unsigned long long r;
    asm("mov.b64 %0, {%1, %2};" : "=l"(r) : "f"(x), "f"(y));
    return r;
}
__device__ __forceinline__ void unpack2(unsigned long long v, float& x, float& y)
{
    asm("mov.b64 {%0, %1}, %2;" : "=f"(x), "=f"(y) : "l"(v));
}
__device__ __forceinline__ float4 ldg_cg(const float4* p)   // L2-only row load
{
    float4 v;
    asm("ld.global.cg.v4.f32 {%0,%1,%2,%3}, [%4];"
        : "=f"(v.x), "=f"(v.y), "=f"(v.z), "=f"(v.w) : "l"(p));
    return v;
}
__device__ __forceinline__ void stg_cs(float4* p, float4 v) // streaming store
{
    asm volatile("st.global.cs.v4.f32 [%0], {%1,%2,%3,%4};"
                 :: "l"(p), "f"(v.x), "f"(v.y), "f"(v.z), "f"(v.w) : "memory");
}

// ---------------------------------------------------------------------------
// Persistent warp-specialized kernel with work stealing.
//   producers (warps 0-3): steal 8-node tile, gather+mean -> As_t[p], ready(p)
//   consumers (warps 4-7): wait ready(p), GEMM vs W + bias, store, free(p)
// Named barriers: 1/2 = buffer ready, 3/4 = buffer free, 5 = producer internal.
// ---------------------------------------------------------------------------
__global__ __launch_bounds__(NTHR, 4) void spa_persist_kernel(
    const float* __restrict__ table,   // [N, 128]
    const float* __restrict__ W,       // [128, 128]
    const float* __restrict__ bias,    // [128]
    const int*   __restrict__ idx,     // [B, 32] int32
    float*       __restrict__ out,     // [B, 128]
    int ntiles)
{
    extern __shared__ char smem[];
    int*   blkslot = reinterpret_cast<int*>  (smem + SMEM_BLK);  // [2]
    float* As_t    = reinterpret_cast<float*>(smem + SMEM_AT);   // [2][128][ATP]
    int*   sidx    = reinterpret_cast<int*>  (smem + SMEM_IDX);  // [8][32]

    const int tid  = threadIdx.x;
    const int lane = tid & 31;
    const int warp = tid >> 5;

    if (warp < 4) {
        // ========================= PRODUCERS ================================
        int p = 0;
        for (;;) {
            // wait buffer p free (consumers pre-arrive for first 2 iterations)
            if (p == 0) asm volatile("bar.sync 3, 256;" ::: "memory");
            else        asm volatile("bar.sync 4, 256;" ::: "memory");

            if (tid == 0) blkslot[p] = (int)atomicAdd(&g_ctr, 1u);
            asm volatile("bar.sync 5, 128;" ::: "memory");
            const int blk = blkslot[p];
            const bool valid = (blk < ntiles);

            if (valid) {
                // stage this tile's 256 indices (threads 0..63, int4 each)
                if (tid < 64) {
                    int4 v = __ldg(reinterpret_cast<const int4*>(
                                       idx + (size_t)blk * (TNODES * KNBR)) + tid);
                    v.x = min(max(v.x, 0), NTBL - 1);
                    v.y = min(max(v.y, 0), NTBL - 1);
                    v.z = min(max(v.z, 0), NTBL - 1);
                    v.w = min(max(v.w, 0), NTBL - 1);
                    reinterpret_cast<int4*>(sidx)[tid] = v;
                }
                asm volatile("bar.sync 5, 128;" ::: "memory");

                float* At = As_t + p * (128 * ATP);
                #pragma unroll 1
                for (int i = 0; i < 2; ++i) {
                    const int c = warp * 2 + i;            // node 0..7 in tile
                    const int* nix = sidx + c * KNBR;
                    unsigned long long aA0 = 0, aA1 = 0, aB0 = 0, aB1 = 0;
                    #pragma unroll
                    for (int k = 0; k < KNBR; k += 2) {
                        const float4 v0 = ldg_cg(reinterpret_cast<const float4*>(
                                              table + (size_t)nix[k] * FDIM) + lane);
                        const float4 v1 = ldg_cg(reinterpret_cast<const float4*>(
                                              table + (size_t)nix[k + 1] * FDIM) + lane);
                        aA0 = add2(aA0, pack2(v0.x, v0.y));
                        aA1 = add2(aA1, pack2(v0.z, v0.w));
                        aB0 = add2(aB0, pack2(v1.x, v1.y));
                        aB1 = add2(aB1, pack2(v1.z, v1.w));
                    }
                    float x0, x1, x2, x3, y0, y1, y2, y3;
                    unpack2(aA0, x0, x1); unpack2(aA1, x2, x3);
                    unpack2(aB0, y0, y1); unpack2(aB1, y2, y3);
                    const float s = 1.0f / (float)KNBR;
                    float* basep = At + (4 * lane) * ATP + c;   // k-major store
                    basep[0 * ATP] = (x0 + y0) * s;
                    basep[1 * ATP] = (x1 + y1) * s;
                    basep[2 * ATP] = (x2 + y2) * s;
                    basep[3 * ATP] = (x3 + y3) * s;
                }
            }
            // signal buffer p ready (sentinel travels via blkslot)
            if (p == 0) asm volatile("bar.arrive 1, 256;" ::: "memory");
            else        asm volatile("bar.arrive 2, 256;" ::: "memory");
            if (!valid) break;
            p ^= 1;
        }
    } else {
        // ========================= CONSUMERS ================================
        // pre-arrive both buffer-free barriers so producers start immediately
        asm volatile("bar.arrive 3, 256;" ::: "memory");
        asm volatile("bar.arrive 4, 256;" ::: "memory");

        const int w4 = warp - 4;              // 0..3: nodes w4*2, w4*2+1
        const int tx = lane;
        const float4* wp = reinterpret_cast<const float4*>(W) + tx;
        const float4 bb = *reinterpret_cast<const float4*>(bias + tx * 4);

        int p = 0;
        for (;;) {
            if (p == 0) asm volatile("bar.sync 1, 256;" ::: "memory");
            else        asm volatile("bar.sync 2, 256;" ::: "memory");

            const int blk = blkslot[p];
            if (blk >= ntiles) break;

            const float* At = As_t + p * (128 * ATP);
            unsigned long long acc2[4];
            #pragma unroll
            for (int j = 0; j < 4; ++j) acc2[j] = 0ull;

            #pragma unroll 8
            for (int k = 0; k < FDIM; ++k) {
                const float4 bv = __ldg(wp + k * 32);     // L1-resident after tile 1
                const unsigned long long av = *reinterpret_cast<const unsigned long long*>(
                    At + k * ATP + w4 * 2);               // LDS.64 broadcast
                acc2[0] = ffma2(av, pack2(bv.x, bv.x), acc2[0]);
                acc2[1] = ffma2(av, pack2(bv.y, bv.y), acc2[1]);
                acc2[2] = ffma2(av, pack2(bv.z, bv.z), acc2[2]);
                acc2[3] = ffma2(av, pack2(bv.w, bv.w), acc2[3]);
            }

            const int m0 = blk * TNODES + w4 * 2;
            float4 o0, o1;
            float lo, hi;
            unpack2(acc2[0], lo, hi); o0.x = lo + bb.x; o1.x = hi + bb.x;
            unpack2(acc2[1], lo, hi); o0.y = lo + bb.y; o1.y = hi + bb.y;
            unpack2(acc2[2], lo, hi); o0.z = lo + bb.z; o1.z = hi + bb.z;
            unpack2(acc2[3], lo, hi); o0.w = lo + bb.w; o1.w = hi + bb.w;
            stg_cs(reinterpret_cast<float4*>(out + (size_t)m0 * EDIM + tx * 4), o0);
            stg_cs(reinterpret_cast<float4*>(out + (size_t)(m0 + 1) * EDIM + tx * 4), o1);

            if (p == 0) asm volatile("bar.arrive 3, 256;" ::: "memory");
            else        asm volatile("bar.arrive 4, 256;" ::: "memory");
            p ^= 1;
        }
    }
}

// ---------------------------------------------------------------------------
// Launch. Inputs: id2feat f32 [N,128], weight f32 [128,128], bias f32 [128],
// neigh_idx int32 [B,32]. Output f32 [B,128].
// ---------------------------------------------------------------------------
extern "C" void kernel_launch(void* const* d_in, const int* in_sizes, int n_in,
                              void* d_out, int out_size)
{
    const float* id2feat = (const float*)d_in[0];
    const float* weight  = (const float*)d_in[1];
    const float* bias    = (const float*)d_in[2];
    const int*   nidx    = (const int*)d_in[3];
    float*       out     = (float*)d_out;

    const int B = in_sizes[3] / KNBR;
    const int ntiles = B / TNODES;

    spa_zero_ctr<<<1, 1>>>();
    cudaFuncSetAttribute(spa_persist_kernel,
                         cudaFuncAttributeMaxDynamicSharedMemorySize, SMEM_TOT);
    spa_persist_kernel<<<GRID, NTHR, SMEM_TOT>>>(
        id2feat, weight, bias, nidx, out, ntiles);
}

// round 13
// speedup vs baseline: 1.0351x; 1.0351x over previous
#include <cuda_runtime.h>
#include <cuda_bf16.h>
#include <cstdint>

// Problem constants (SpaAggregator): B=16384, K=32, N=1e6, F=E=128
#define KNBR 32
#define FDIM 128
#define EDIM 128
#define NTBL 1000000

#define BM     32        // nodes per CTA -> grid = 512
#define NTHR   256       // 8 warps: 4 producer + 4 consumer
#define NTILE  4         // pipeline tiles per CTA
#define TNODES 8         // nodes per tile
#define ATP    10        // As_t node-dim stride (floats); k-stride 40B, pairs 8B-aligned

// smem (bytes): As_t ring 4*128*10*4 = 20480 ; sidx 32*32*4 = 4096
#define SMEM_AT   0
#define SMEM_IDX  20480
#define SMEM_TOT  (20480 + 4096)

__device__ __forceinline__ unsigned long long ffma2(
    unsigned long long a, unsigned long long b, unsigned long long c)
{
    unsigned long long d;
    asm("fma.rn.f32x2 %0, %1, %2, %3;" : "=l"(d) : "l"(a), "l"(b), "l"(c));
    return d;
}
__device__ __forceinline__ unsigned long long add2(
    unsigned long long a, unsigned long long b)
{
    unsigned long long d;
    asm("add.rn.f32x2 %0, %1, %2;" : "=l"(d) : "l"(a), "l"(b));
    return d;
}
__device__ __forceinline__ unsigned long long pack2(float x, float y)
{
    unsigned long long r;
    asm("mov.b64 %0, {%1, %2};" : "=l"(r) : "f"(x), "f"(y));
    return r;
}
__device__ __forceinline__ void unpack2(unsigned long long v, float& x, float& y)
{
    asm("mov.b64 {%0, %1}, %2;" : "=f"(x), "=f"(y) : "l"(v));
}
// table row load: L2-only (no L1 allocation; rows have zero L1 reuse)
__device__ __forceinline__ float4 ldg_cg(const float4* p)
{
    float4 v;
    asm("ld.global.cg.v4.f32 {%0,%1,%2,%3}, [%4];"
        : "=f"(v.x), "=f"(v.y), "=f"(v.z), "=f"(v.w) : "l"(p));
    return v;
}
// output store: streaming (evict-first) — don't displace table rows in L2
__device__ __forceinline__ void stg_cs(float4* p, float4 v)
{
    asm volatile("st.global.cs.v4.f32 [%0], {%1,%2,%3,%4};"
                 :: "l"(p), "f"(v.x), "f"(v.y), "f"(v.z), "f"(v.w) : "memory");
}

// ---------------------------------------------------------------------------
// Warp-specialized fused kernel, 4-stage pipeline (R11 memory ops):
//   warps 0-3 (producers): gather+mean 8-node tiles -> As_t ring, bar.arrive
//   warps 4-7 (consumers): bar.sync tile, GEMM vs W (L1/L2) + bias, .cs store
// ---------------------------------------------------------------------------
__global__ __launch_bounds__(NTHR, 4) void spa_fused_ws4_kernel(
    const float* __restrict__ table,   // [N, 128]
    const float* __restrict__ W,       // [128, 128]
    const float* __restrict__ bias,    // [128]
    const int*   __restrict__ idx,     // [B, 32] int32
    float*       __restrict__ out,     // [B, 128]
    int B)
{
    extern __shared__ char smem[];
    float* As_t = reinterpret_cast<float*>(smem + SMEM_AT);   // [4][128][ATP]
    int*   sidx = reinterpret_cast<int*>  (smem + SMEM_IDX);  // [32][32]

    const int tid   = threadIdx.x;
    const int lane  = tid & 31;
    const int warp  = tid >> 5;
    const int blk_m = blockIdx.x * BM;

    // --- stage indices: 1024 ints, int4 per thread (all warps) -------------
    {
        const int4* ip = reinterpret_cast<const int4*>(idx + (size_t)blk_m * KNBR);
        int4 v = __ldg(ip + tid);
        v.x = min(max(v.x, 0), NTBL - 1);
        v.y = min(max(v.y, 0), NTBL - 1);
        v.z = min(max(v.z, 0), NTBL - 1);
        v.w = min(max(v.w, 0), NTBL - 1);
        reinterpret_cast<int4*>(sidx)[tid] = v;
    }
    __syncthreads();

    if (warp < 4) {
        // =============== PRODUCER: gather + mean ===========================
        // tile t: nodes [t*8, t*8+8); this warp: 2 nodes per tile.
        #pragma unroll 1
        for (int t = 0; t < NTILE; ++t) {
            float* At = As_t + t * (128 * ATP);
            #pragma unroll 1
            for (int i = 0; i < 2; ++i) {
                const int c  = warp * 2 + i;          // node within tile 0..7
                const int ln = t * TNODES + c;        // local node 0..31
                const int* nix = sidx + ln * KNBR;
                unsigned long long aA0 = 0, aA1 = 0, aB0 = 0, aB1 = 0;
                #pragma unroll
                for (int k = 0; k < KNBR; k += 2) {
                    const float4 v0 = ldg_cg(reinterpret_cast<const float4*>(
                                          table + (size_t)nix[k] * FDIM) + lane);
                    const float4 v1 = ldg_cg(reinterpret_cast<const float4*>(
                                          table + (size_t)nix[k + 1] * FDIM) + lane);
                    aA0 = add2(aA0, pack2(v0.x, v0.y));
                    aA1 = add2(aA1, pack2(v0.z, v0.w));
                    aB0 = add2(aB0, pack2(v1.x, v1.y));
                    aB1 = add2(aB1, pack2(v1.z, v1.w));
                }
                float x0, x1, x2, x3, y0, y1, y2, y3;
                unpack2(aA0, x0, x1); unpack2(aA1, x2, x3);
                unpack2(aB0, y0, y1); unpack2(aB1, y2, y3);
                const float s = 1.0f / (float)KNBR;
                float* basep = At + (4 * lane) * ATP + c;   // k-major store
                basep[0 * ATP] = (x0 + y0) * s;
                basep[1 * ATP] = (x1 + y1) * s;
                basep[2 * ATP] = (x2 + y2) * s;
                basep[3 * ATP] = (x3 + y3) * s;
            }
            // signal tile t ready (named barrier t+1, total count 256)
            switch (t) {
                case 0: asm volatile("bar.arrive 1, 256;" ::: "memory"); break;
                case 1: asm volatile("bar.arrive 2, 256;" ::: "memory"); break;
                case 2: asm volatile("bar.arrive 3, 256;" ::: "memory"); break;
                default:asm volatile("bar.arrive 4, 256;" ::: "memory"); break;
            }
        }
    } else {
        // =============== CONSUMER: GEMM + bias + store ======================
        const int w4 = warp - 4;                 // 0..3: nodes w4*2, w4*2+1 of tile
        const int tx = lane;
        const float4* wp = reinterpret_cast<const float4*>(W) + tx;  // W[k][4tx..]
        const float4 bb = *reinterpret_cast<const float4*>(bias + tx * 4);

        #pragma unroll 1
        for (int t = 0; t < NTILE; ++t) {
            switch (t) {
                case 0: asm volatile("bar.sync 1, 256;" ::: "memory"); break;
                case 1: asm volatile("bar.sync 2, 256;" ::: "memory"); break;
                case 2: asm volatile("bar.sync 3, 256;" ::: "memory"); break;
                default:asm volatile("bar.sync 4, 256;" ::: "memory"); break;
            }

            const float* At = As_t + t * (128 * ATP);
            unsigned long long acc2[4];
            #pragma unroll
            for (int j = 0; j < 4; ++j) acc2[j] = 0ull;

            #pragma unroll 8
            for (int k = 0; k < FDIM; ++k) {
                const float4 bv = __ldg(wp + k * 32);
                // a: 2 nodes = 1 packed pair, LDS.64 broadcast (same addr all lanes)
                const unsigned long long av = *reinterpret_cast<const unsigned long long*>(
                    At + k * ATP + w4 * 2);
                acc2[0] = ffma2(av, pack2(bv.x, bv.x), acc2[0]);
                acc2[1] = ffma2(av, pack2(bv.y, bv.y), acc2[1]);
                acc2[2] = ffma2(av, pack2(bv.z, bv.z), acc2[2]);
                acc2[3] = ffma2(av, pack2(bv.w, bv.w), acc2[3]);
            }

            const int m0 = blk_m + t * TNODES + w4 * 2;
            float4 o0, o1;
            float lo, hi;
            unpack2(acc2[0], lo, hi); o0.x = lo + bb.x; o1.x = hi + bb.x;
            unpack2(acc2[1], lo, hi); o0.y = lo + bb.y; o1.y = hi + bb.y;
            unpack2(acc2[2], lo, hi); o0.z = lo + bb.z; o1.z = hi + bb.z;
            unpack2(acc2[3], lo, hi); o0.w = lo + bb.w; o1.w = hi + bb.w;
            stg_cs(reinterpret_cast<float4*>(out + (size_t)m0 * EDIM + tx * 4), o0);
            stg_cs(reinterpret_cast<float4*>(out + (size_t)(m0 + 1) * EDIM + tx * 4), o1);
        }
    }
}

// ---------------------------------------------------------------------------
// Launch. Inputs: id2feat f32 [N,128], weight f32 [128,128], bias f32 [128],
// neigh_idx int32 [B,32]. Output f32 [B,128].
// ---------------------------------------------------------------------------
extern "C" void kernel_launch(void* const* d_in, const int* in_sizes, int n_in,
                              void* d_out, int out_size)
{
    const float* id2feat = (const float*)d_in[0];
    const float* weight  = (const float*)d_in[1];
    const float* bias    = (const float*)d_in[2];
    const int*   nidx    = (const int*)d_in[3];
    float*       out     = (float*)d_out;

    const int B = in_sizes[3] / KNBR;

    cudaFuncSetAttribute(spa_fused_ws4_kernel,
                         cudaFuncAttributeMaxDynamicSharedMemorySize, SMEM_TOT);
    spa_fused_ws4_kernel<<<(B + BM - 1) / BM, NTHR, SMEM_TOT>>>(
        id2feat, weight, bias, nidx, out, B);
}

// round 14
// speedup vs baseline: 1.0500x; 1.0144x over previous
#include <cuda_runtime.h>
#include <cuda_bf16.h>
#include <cstdint>

// Problem constants (SpaAggregator): B=16384, K=32, N=1e6, F=E=128
#define KNBR 32
#define FDIM 128
#define EDIM 128
#define NTBL 1000000

#define BM    32         // nodes per CTA -> grid = 512 for B=16384
#define NTHR  256        // 8 warps: 4 producer + 4 consumer
#define TILE  16         // nodes per pipeline tile (2 tiles per CTA)
#define ATP   20         // As_t row stride in floats (16 + pad; 80B, 16B-aligned)

// Dynamic smem (bytes): As_t[2] tiles 2*128*20*4 = 20480 ; sidx 32*32*4 = 4096
#define SMEM_AT   0
#define SMEM_IDX  20480
#define SMEM_TOT  (20480 + 4096)

__device__ __forceinline__ unsigned long long ffma2(
    unsigned long long a, unsigned long long b, unsigned long long c)
{
    unsigned long long d;
    asm("fma.rn.f32x2 %0, %1, %2, %3;" : "=l"(d) : "l"(a), "l"(b), "l"(c));
    return d;
}
__device__ __forceinline__ unsigned long long add2(
    unsigned long long a, unsigned long long b)
{
    unsigned long long d;
    asm("add.rn.f32x2 %0, %1, %2;" : "=l"(d) : "l"(a), "l"(b));
    return d;
}
__device__ __forceinline__ unsigned long long pack2(float x, float y)
{
    unsigned long long r;
    asm("mov.b64 %0, {%1, %2};" : "=l"(r) : "f"(x), "f"(y));
    return r;
}
__device__ __forceinline__ void unpack2(unsigned long long v, float& x, float& y)
{
    asm("mov.b64 {%0, %1}, %2;" : "=f"(x), "=f"(y) : "l"(v));
}
// table row load: L2-only (no L1 allocation; rows have zero L1 reuse)
__device__ __forceinline__ float4 ldg_cg(const float4* p)
{
    float4 v;
    asm("ld.global.cg.v4.f32 {%0,%1,%2,%3}, [%4];"
        : "=f"(v.x), "=f"(v.y), "=f"(v.z), "=f"(v.w) : "l"(p));
    return v;
}
// output store: streaming (evict-first) — don't displace table rows in L2
__device__ __forceinline__ void stg_cs(float4* p, float4 v)
{
    asm volatile("st.global.cs.v4.f32 [%0], {%1,%2,%3,%4};"
                 :: "l"(p), "f"(v.x), "f"(v.y), "f"(v.z), "f"(v.w) : "memory");
}

// ---------------------------------------------------------------------------
// Warp-specialized fused kernel (converged best form):
//   warps 0-3: gather + mean -> As_t tile ring (k-major), bar.arrive
//   warps 4-7: bar.sync, GEMM tile vs W (L1/L2), +bias, streaming store
// Duration == DRAM bytes / random-512B service rate: memory-pattern roofline.
// ---------------------------------------------------------------------------
__global__ __launch_bounds__(NTHR, 4) void spa_fused_ws_kernel(
    const float* __restrict__ table,   // [N, 128]
    const float* __restrict__ W,       // [128, 128]
    const float* __restrict__ bias,    // [128]
    const int*   __restrict__ idx,     // [B, 32] int32
    float*       __restrict__ out,     // [B, 128]
    int B)
{
    extern __shared__ char smem[];
    float* As_t = reinterpret_cast<float*>(smem + SMEM_AT);   // [2][128][ATP]
    int*   sidx = reinterpret_cast<int*>  (smem + SMEM_IDX);  // [32][32]

    const int tid   = threadIdx.x;
    const int lane  = tid & 31;
    const int warp  = tid >> 5;
    const int blk_m = blockIdx.x * BM;

    // --- stage indices: 1024 ints, int4 per thread (all warps) -------------
    {
        const int4* ip = reinterpret_cast<const int4*>(idx + (size_t)blk_m * KNBR);
        int4 v = __ldg(ip + tid);
        v.x = min(max(v.x, 0), NTBL - 1);
        v.y = min(max(v.y, 0), NTBL - 1);
        v.z = min(max(v.z, 0), NTBL - 1);
        v.w = min(max(v.w, 0), NTBL - 1);
        reinterpret_cast<int4*>(sidx)[tid] = v;
    }
    __syncthreads();

    if (warp < 4) {
        // =============== PRODUCER: gather + mean ===========================
        // tile t: nodes [t*16, t*16+16); this warp: 4 nodes per tile.
        #pragma unroll 1
        for (int t = 0; t < 2; ++t) {
            float* At = As_t + t * (128 * ATP);
            #pragma unroll 1
            for (int i = 0; i < TILE / 4; ++i) {
                const int c  = warp * 4 + i;          // column within tile
                const int ln = t * TILE + c;          // local node 0..31
                const int* nix = sidx + ln * KNBR;
                unsigned long long aA0 = 0, aA1 = 0, aB0 = 0, aB1 = 0;
                #pragma unroll
                for (int k = 0; k < KNBR; k += 2) {
                    const float4 v0 = ldg_cg(reinterpret_cast<const float4*>(
                                          table + (size_t)nix[k] * FDIM) + lane);
                    const float4 v1 = ldg_cg(reinterpret_cast<const float4*>(
                                          table + (size_t)nix[k + 1] * FDIM) + lane);
                    aA0 = add2(aA0, pack2(v0.x, v0.y));
                    aA1 = add2(aA1, pack2(v0.z, v0.w));
                    aB0 = add2(aB0, pack2(v1.x, v1.y));
                    aB1 = add2(aB1, pack2(v1.z, v1.w));
                }
                float x0, x1, x2, x3, y0, y1, y2, y3;
                unpack2(aA0, x0, x1); unpack2(aA1, x2, x3);
                unpack2(aB0, y0, y1); unpack2(aB1, y2, y3);
                const float s = 1.0f / (float)KNBR;
                float* base = At + (4 * lane) * ATP + c;   // k-major store
                base[0 * ATP] = (x0 + y0) * s;
                base[1 * ATP] = (x1 + y1) * s;
                base[2 * ATP] = (x2 + y2) * s;
                base[3 * ATP] = (x3 + y3) * s;
            }
            // signal tile t ready (barrier id t+1, total count = 256)
            if (t == 0) asm volatile("bar.arrive 1, 256;" ::: "memory");
            else        asm volatile("bar.arrive 2, 256;" ::: "memory");
        }
    } else {
        // =============== CONSUMER: GEMM + bias + store ======================
        const int w4 = warp - 4;                 // 0..3: rows w4*4..+3 of tile
        const int tx = lane;
        const float4* wp = reinterpret_cast<const float4*>(W) + tx;  // W[k][4tx..]
        const float4 bb = *reinterpret_cast<const float4*>(bias + tx * 4);

        #pragma unroll 1
        for (int t = 0; t < 2; ++t) {
            if (t == 0) asm volatile("bar.sync 1, 256;" ::: "memory");
            else        asm volatile("bar.sync 2, 256;" ::: "memory");

            const float* At = As_t + t * (128 * ATP);
            unsigned long long acc2[2][4];
            #pragma unroll
            for (int p = 0; p < 2; ++p)
                #pragma unroll
                for (int j = 0; j < 4; ++j) acc2[p][j] = 0ull;

            #pragma unroll 8
            for (int k = 0; k < FDIM; ++k) {
                const float4 bv = __ldg(wp + k * 32);
                // a: 4 consecutive nodes = 2 packed pairs, one LDS.128 (broadcast)
                const ulonglong2 av = *reinterpret_cast<const ulonglong2*>(
                    At + k * ATP + w4 * 4);
                unsigned long long b2[4];
                b2[0] = pack2(bv.x, bv.x);
                b2[1] = pack2(bv.y, bv.y);
                b2[2] = pack2(bv.z, bv.z);
                b2[3] = pack2(bv.w, bv.w);
                #pragma unroll
                for (int j = 0; j < 4; ++j) {
                    acc2[0][j] = ffma2(av.x, b2[j], acc2[0][j]);
                    acc2[1][j] = ffma2(av.y, b2[j], acc2[1][j]);
                }
            }

            #pragma unroll
            for (int p = 0; p < 2; ++p) {
                const int m0 = blk_m + t * TILE + w4 * 4 + 2 * p;
                float4 o0, o1;
                float lo, hi;
                unpack2(acc2[p][0], lo, hi); o0.x = lo + bb.x; o1.x = hi + bb.x;
                unpack2(acc2[p][1], lo, hi); o0.y = lo + bb.y; o1.y = hi + bb.y;
                unpack2(acc2[p][2], lo, hi); o0.z = lo + bb.z; o1.z = hi + bb.z;
                unpack2(acc2[p][3], lo, hi); o0.w = lo + bb.w; o1.w = hi + bb.w;
                stg_cs(reinterpret_cast<float4*>(out + (size_t)m0 * EDIM + tx * 4), o0);
                stg_cs(reinterpret_cast<float4*>(out + (size_t)(m0 + 1) * EDIM + tx * 4), o1);
            }
        }
    }
}

// ---------------------------------------------------------------------------
// Launch. Inputs: id2feat f32 [N,128], weight f32 [128,128], bias f32 [128],
// neigh_idx int32 [B,32]. Output f32 [B,128].
// ---------------------------------------------------------------------------
extern "C" void kernel_launch(void* const* d_in, const int* in_sizes, int n_in,
                              void* d_out, int out_size)
{
    const float* id2feat = (const float*)d_in[0];
    const float* weight  = (const float*)d_in[1];
    const float* bias    = (const float*)d_in[2];
    const int*   nidx    = (const int*)d_in[3];
    float*       out     = (float*)d_out;

    const int B = in_sizes[3] / KNBR;

    cudaFuncSetAttribute(spa_fused_ws_kernel,
                         cudaFuncAttributeMaxDynamicSharedMemorySize, SMEM_TOT);
    spa_fused_ws_kernel<<<(B + BM - 1) / BM, NTHR, SMEM_TOT>>>(
        id2feat, weight, bias, nidx, out, B);
}